// round 11
// baseline (speedup 1.0000x reference)
#include <cuda_runtime.h>
#include <stdint.h>
#include <math.h>

#define Bimg 16
#define Nbox 16
#define Him  640
#define Wim  640
#define PHp  300
#define PWp  300
#define PTOT (PHp*PWp*3)
#define IMG  ((size_t)Him * Wim * 3)

// ---------------------------------------------------------------------------
// JAX threefry2x32 (20 rounds), partitionable random-bits convention
// ---------------------------------------------------------------------------
__device__ __forceinline__ void tf2x32(uint32_t k0, uint32_t k1,
                                       uint32_t x0, uint32_t x1,
                                       uint32_t& o0, uint32_t& o1) {
    uint32_t ks2 = k0 ^ k1 ^ 0x1BD11BDAu;
    x0 += k0; x1 += k1;
#define TF_RND(r) { x0 += x1; x1 = __funnelshift_l(x1, x1, (r)); x1 ^= x0; }
    TF_RND(13) TF_RND(15) TF_RND(26) TF_RND(6)
    x0 += k1;  x1 += ks2 + 1u;
    TF_RND(17) TF_RND(29) TF_RND(16) TF_RND(24)
    x0 += ks2; x1 += k0 + 2u;
    TF_RND(13) TF_RND(15) TF_RND(26) TF_RND(6)
    x0 += k0;  x1 += k1 + 3u;
    TF_RND(17) TF_RND(29) TF_RND(16) TF_RND(24)
    x0 += k1;  x1 += ks2 + 4u;
    TF_RND(13) TF_RND(15) TF_RND(26) TF_RND(6)
    x0 += ks2; x1 += k0 + 5u;
#undef TF_RND
    o0 = x0; o1 = x1;
}

__device__ __forceinline__ uint32_t rbits(uint32_t k0, uint32_t k1, uint64_t idx) {
    uint32_t a, b;
    tf2x32(k0, k1, (uint32_t)(idx >> 32), (uint32_t)idx, a, b);
    return a ^ b;
}

// 3 interleaved threefry chains, counters (c0, c0+1, c0+2), hi word = 0.
__device__ __forceinline__ void tf3(uint32_t k0, uint32_t k1, uint32_t c0,
                                    uint32_t out[3]) {
    uint32_t ks2 = k0 ^ k1 ^ 0x1BD11BDAu;
    uint32_t a0 = k0, a1 = k0, a2 = k0;
    uint32_t b0 = c0 + k1, b1 = c0 + 1u + k1, b2 = c0 + 2u + k1;
#define R3(r)  { a0 += b0; b0 = __funnelshift_l(b0,b0,(r)); b0 ^= a0; \
                 a1 += b1; b1 = __funnelshift_l(b1,b1,(r)); b1 ^= a1; \
                 a2 += b2; b2 = __funnelshift_l(b2,b2,(r)); b2 ^= a2; }
#define INJ3(ka, kb) { a0 += (ka); b0 += (kb); a1 += (ka); b1 += (kb); a2 += (ka); b2 += (kb); }
    R3(13) R3(15) R3(26) R3(6)
    INJ3(k1, ks2 + 1u)
    R3(17) R3(29) R3(16) R3(24)
    INJ3(ks2, k0 + 2u)
    R3(13) R3(15) R3(26) R3(6)
    INJ3(k0, k1 + 3u)
    R3(17) R3(29) R3(16) R3(24)
    INJ3(k1, ks2 + 4u)
    R3(13) R3(15) R3(26) R3(6)
    out[0] = (a0 + ks2) ^ (b0 + k0 + 5u);
    out[1] = (a1 + ks2) ^ (b1 + k0 + 5u);
    out[2] = (a2 + ks2) ^ (b2 + k0 + 5u);
#undef R3
#undef INJ3
}

__device__ __forceinline__ float bits_to_unit(uint32_t bits) {
    return __uint_as_float((bits >> 9) | 0x3f800000u) - 1.0f;
}

__device__ __forceinline__ float juniform(uint32_t k0, uint32_t k1, uint64_t i,
                                          float lo, float hi) {
    float f = bits_to_unit(rbits(k0, k1, i));
    return fmaxf(lo, f * (hi - lo) + lo);
}

__device__ __forceinline__ float erfinv_xla(float x) {
    float w = -log1pf(-x * x);
    float p;
    if (w < 5.0f) {
        w -= 2.5f;
        p = 2.81022636e-08f;
        p = fmaf(p, w, 3.43273939e-07f);
        p = fmaf(p, w, -3.5233877e-06f);
        p = fmaf(p, w, -4.39150654e-06f);
        p = fmaf(p, w, 0.00021858087f);
        p = fmaf(p, w, -0.00125372503f);
        p = fmaf(p, w, -0.00417768164f);
        p = fmaf(p, w, 0.246640727f);
        p = fmaf(p, w, 1.50140941f);
    } else {
        w = sqrtf(w) - 3.0f;
        p = -0.000200214257f;
        p = fmaf(p, w, 0.000100950558f);
        p = fmaf(p, w, 0.00134934322f);
        p = fmaf(p, w, -0.00367342844f);
        p = fmaf(p, w, 0.00573950773f);
        p = fmaf(p, w, -0.0076224613f);
        p = fmaf(p, w, 0.00943887047f);
        p = fmaf(p, w, 1.00167406f);
        p = fmaf(p, w, 2.83297682f);
    }
    return p * x;
}

__device__ __forceinline__ float jnormal(uint32_t k0, uint32_t k1, uint64_t i) {
    const float lo = -0.99999994f;
    float u = juniform(k0, k1, i, lo, 1.0f);
    return 1.41421354f * erfinv_xla(u);
}

__device__ __forceinline__ void wb_for(int b, float w[3], float bb[3]) {
    uint32_t ib0, ib1;
    tf2x32(0u, 42u, 0u, (uint32_t)b, ib0, ib1);
    uint32_t kw0, kw1, kB0, kB1;
    tf2x32(ib0, ib1, 0u, 0u, kw0, kw1);
    tf2x32(ib0, ib1, 0u, 1u, kB0, kB1);
    #pragma unroll
    for (int c = 0; c < 3; c++) {
        w[c]  = jnormal(kw0, kw1, (uint64_t)c) * 0.1f + 0.5f;
        bb[c] = jnormal(kB0, kB1, (uint64_t)c) * 0.01f;
    }
}

// ---------------------------------------------------------------------------
// Device scratch
// ---------------------------------------------------------------------------
struct Geo {
    float y0i, x0i, diagi, phi, cc, top, r, ca, sa, bright;
    uint32_t k2a, k2b;
    int valid;
    int pad;
};                                      // 14 words

#define NIMG_CHUNK 300
#define NPAT_CHUNK 16

__device__ Geo      g_geo[Bimg][Nbox];
__device__ float    g_w[Bimg][3];
__device__ float    g_bj[Bimg][3];
__device__ float    g_isum[Bimg][NIMG_CHUNK];
__device__ float    g_psum[Bimg][NPAT_CHUNK];
__device__ float    g_s[Bimg];
__device__ unsigned g_later[Bimg][Nbox];

// ---------------------------------------------------------------------------
// K1 (k_prep): streaming copy+zero with fused image sums; patch sums;
// geometry + later-writer masks. grid (300+16+1, 16), 256 thr.
// Copy blocks: exactly 1024 float4 each (4 per thread, no loop, no tail).
// ---------------------------------------------------------------------------
__global__ void __launch_bounds__(256)
k_prep(const float* __restrict__ images,
       const float* __restrict__ patch,
       const float* __restrict__ boxes,
       const float* __restrict__ scale_p,
       float* __restrict__ oimg,
       float* __restrict__ omask) {
    int b = blockIdx.y, g = blockIdx.x;

    if (g == NIMG_CHUNK + NPAT_CHUNK) {
        __shared__ Geo sgeo[Nbox];
        int n = threadIdx.x;
        if (n == 0) {
            float w[3], bb[3];
            wb_for(b, w, bb);
            #pragma unroll
            for (int c = 0; c < 3; c++) { g_w[b][c] = w[c]; g_bj[b][c] = bb[c]; }
        }
        if (n < Nbox) {
            float scale = scale_p[0];
            uint32_t ib0, ib1, kl0, kl1;
            tf2x32(0u, 42u, 0u, (uint32_t)b, ib0, ib1);
            tf2x32(ib0, ib1, 0u, 2u, kl0, kl1);
            uint32_t kn0, kn1;
            tf2x32(kl0, kl1, 0u, (uint32_t)n, kn0, kn1);
            uint32_t k10, k11, k20, k21, k30, k31;
            tf2x32(kn0, kn1, 0u, 0u, k10, k11);
            tf2x32(kn0, kn1, 0u, 1u, k20, k21);
            tf2x32(kn0, kn1, 0u, 2u, k30, k31);

            const float MAXA = (float)(20.0 * 3.14159265358979323846 / 180.0);
            float angle  = juniform(k10, k11, 0ull, -MAXA, MAXA);
            float bright = juniform(k30, k31, 0ull, -0.3f, 0.3f);

            const float* bx = boxes + ((size_t)b * Nbox + n) * 4;
            float ymin = bx[0], xmin = bx[1], ymax = bx[2], xmax = bx[3];
            float h  = ymax - ymin;
            float ww = xmax - xmin;
            float longer = fmaxf(h, ww);
            float ps   = floorf(longer * scale);
            float diag = fminf(sqrtf(2.0f) * ps, (float)Wim);
            float oy = ymin + h * 0.5f;
            float ox = xmin + ww * 0.5f;
            float y0 = fmaxf(oy - diag * 0.5f, 0.0f);
            float x0 = fmaxf(ox - diag * 0.5f, 0.0f);
            y0 = (y0 + diag > (float)Him) ? ((float)Him - diag) : y0;
            x0 = (x0 + diag > (float)Wim) ? ((float)Wim - diag) : x0;
            float phi   = fmaxf(floorf(ps), 1.0f);
            float diagi = floorf(diag);

            Geo gg;
            gg.y0i = floorf(y0); gg.x0i = floorf(x0);
            gg.diagi = diagi; gg.phi = phi;
            gg.cc  = (diagi - 1.0f) * 0.5f;
            gg.top = floorf((diagi - phi) * 0.5f);
            gg.r   = 300.0f / phi;
            gg.ca  = cosf(angle);
            gg.sa  = sinf(angle);
            gg.bright = bright;
            gg.k2a = k20; gg.k2b = k21;
            gg.valid = (phi * phi > 60.0f) ? 1 : 0;
            gg.pad = 0;
            g_geo[b][n] = gg;
            sgeo[n] = gg;
        }
        __syncthreads();
        if (n < Nbox) {
            const Geo& N = sgeo[n];
            unsigned m = 0;
            for (int j = n + 1; j < Nbox; j++) {
                const Geo& J = sgeo[j];
                if (J.valid &&
                    N.y0i < J.y0i + J.diagi && N.y0i + N.diagi > J.y0i &&
                    N.x0i < J.x0i + J.diagi && N.x0i + N.diagi > J.x0i)
                    m |= 1u << j;
            }
            g_later[b][n] = m;
        }
        return;
    }

    float acc;
    if (g < NIMG_CHUNK) {
        // exactly 1024 float4 per block, 4 per thread
        size_t base4 = ((size_t)b * IMG) / 4 + (size_t)g * 1024;
        const float4* src  = (const float4*)images + base4;
        float4* dimg = (float4*)oimg  + base4;
        float4* dmsk = (float4*)omask + base4;
        const float4 z = make_float4(0.f, 0.f, 0.f, 0.f);
        int i = threadIdx.x;
        float4 v0 = __ldcs(src + i);
        float4 v1 = __ldcs(src + i + 256);
        float4 v2 = __ldcs(src + i + 512);
        float4 v3 = __ldcs(src + i + 768);
        __stcs(dimg + i,       v0); __stcs(dimg + i + 256, v1);
        __stcs(dimg + i + 512, v2); __stcs(dimg + i + 768, v3);
        __stcs(dmsk + i,       z);  __stcs(dmsk + i + 256, z);
        __stcs(dmsk + i + 512, z);  __stcs(dmsk + i + 768, z);
        float a0 = (v0.x + v0.y) + (v0.z + v0.w);
        float a1 = (v1.x + v1.y) + (v1.z + v1.w);
        float a2 = (v2.x + v2.y) + (v2.z + v2.w);
        float a3 = (v3.x + v3.y) + (v3.z + v3.w);
        acc = (a0 + a1) + (a2 + a3);
    } else {
        float w[3], bb[3];
        wb_for(b, w, bb);
        int gp = g - NIMG_CHUNK;
        int chunk = PTOT / NPAT_CHUNK;                    // 16875
        int base = gp * chunk;
        float a0 = 0.f, a1 = 0.f;
        int i = base + threadIdx.x;
        int end = base + chunk;
        for (; i + 256 < end; i += 512) {
            int c0 = i % 3;
            int c1 = (i + 256) % 3;
            a0 += fminf(fmaxf(w[c0] * patch[i] + bb[c0], -1.0f), 1.0f);
            a1 += fminf(fmaxf(w[c1] * patch[i + 256] + bb[c1], -1.0f), 1.0f);
        }
        if (i < end) {
            int c = i % 3;
            a0 += fminf(fmaxf(w[c] * patch[i] + bb[c], -1.0f), 1.0f);
        }
        acc = a0 + a1;
    }
    __shared__ float sh[256];
    sh[threadIdx.x] = acc;
    __syncthreads();
    for (int s = 128; s > 32; s >>= 1) {
        if (threadIdx.x < s) sh[threadIdx.x] += sh[threadIdx.x + s];
        __syncthreads();
    }
    if (threadIdx.x < 32) {
        float v = sh[threadIdx.x] + sh[threadIdx.x + 32];
        #pragma unroll
        for (int o = 16; o > 0; o >>= 1)
            v += __shfl_down_sync(0xffffffffu, v, o);
        if (threadIdx.x == 0) {
            if (g < NIMG_CHUNK) g_isum[b][g] = v;
            else                g_psum[b][g - NIMG_CHUNK] = v;
        }
    }
}

// ---------------------------------------------------------------------------
// K2 (k_s): finalize per-image brightness shift. grid (16), 128 thr.
// ---------------------------------------------------------------------------
__global__ void k_s() {
    int b = blockIdx.x;
    int t = threadIdx.x;
    float si = g_isum[b][t] + g_isum[b][t + 128]
             + ((t < NIMG_CHUNK - 256) ? g_isum[b][t + 256] : 0.0f);
    float sp = (t < NPAT_CHUNK) ? g_psum[b][t] : 0.0f;
    __shared__ float shi[128], shp[128];
    shi[t] = si; shp[t] = sp;
    __syncthreads();
    if (t < 64) { shi[t] += shi[t + 64]; shp[t] += shp[t + 64]; }
    __syncthreads();
    if (t < 32) {
        float vi = shi[t] + shi[t + 32];
        float vp = shp[t] + shp[t + 32];
        #pragma unroll
        for (int o = 16; o > 0; o >>= 1) {
            vi += __shfl_down_sync(0xffffffffu, vi, o);
            vp += __shfl_down_sync(0xffffffffu, vp, o);
        }
        if (t == 0) g_s[b] = vi / 1228800.0f - vp / 270000.0f;
    }
}

// ---------------------------------------------------------------------------
// K3 (k_heavy): warp-per-row over each box's diag square. For row u the
// valid-src v-range is an interval (py/px linear in v); lanes cover only a
// conservative superset of it, with the EXACT per-pixel test preserved.
// grid (32, 256), block 128 (4 warps).
// ---------------------------------------------------------------------------
__global__ void k_heavy(const float* __restrict__ images,
                        const float* __restrict__ patch,
                        float* __restrict__ oimg,
                        float* __restrict__ omask) {
    int bz = blockIdx.y;
    int b = bz >> 4, n = bz & 15;

    const Geo G = g_geo[b][n];          // uniform broadcast loads
    if (!G.valid) return;
    int diag = (int)G.diagi;
    int warp = threadIdx.x >> 5;
    int lane = threadIdx.x & 31;

    float s  = g_s[b];
    float w0 = g_w[b][0],  w1 = g_w[b][1],  w2 = g_w[b][2];
    float b0 = g_bj[b][0], b1 = g_bj[b][1], b2 = g_bj[b][2];
    unsigned later = g_later[b][n];
    float lim = G.phi - 1.0f;

    for (int u = blockIdx.x * 4 + warp; u < diag; u += 128) {
        float uf = (float)u;
        // py(v) = P0 - sa*v ; px(v) = Q0 + ca*v   (rearranged ONLY for bounds)
        float P0 = G.cc + G.ca * (uf - G.cc) + G.sa * G.cc - G.top;
        float Q0 = G.cc + G.sa * (uf - G.cc) - G.ca * G.cc - G.top;
        float lo = (0.0f - Q0) / G.ca;
        float hi = (lim  - Q0) / G.ca;
        if (G.sa > 1e-8f) {
            lo = fmaxf(lo, (P0 - lim) / G.sa);
            hi = fminf(hi, P0 / G.sa);
        } else if (G.sa < -1e-8f) {
            lo = fmaxf(lo, P0 / G.sa);
            hi = fminf(hi, (P0 - lim) / G.sa);
        }
        int v0 = max(0, (int)floorf(lo) - 2);
        int v1 = min(diag - 1, (int)ceilf(hi) + 2);

        for (int v = v0 + lane; v <= v1; v += 32) {
            float vf = (float)v;
            // EXACT valid_src test (identical expression to prior rounds)
            float um = uf - G.cc, vm = vf - G.cc;
            float py = G.cc + G.ca * um - G.sa * vm - G.top;
            float px = G.cc + G.sa * um + G.ca * vm - G.top;
            if (!(py >= 0.0f && py <= lim && px >= 0.0f && px <= lim)) continue;

            // skip if any LATER box also writes this pixel
            {
                float yab = G.y0i + uf, xab = G.x0i + vf;
                unsigned mm = later;
                bool taken = false;
                while (mm) {
                    int j = __ffs(mm) - 1;
                    mm &= mm - 1;
                    const Geo J = g_geo[b][j];
                    float uj = yab - J.y0i, vj = xab - J.x0i;
                    if (uj >= 0.f && vj >= 0.f && uj < J.diagi && vj < J.diagi) {
                        float umj = uj - J.cc, vmj = vj - J.cc;
                        float pyj = J.cc + J.ca * umj - J.sa * vmj - J.top;
                        float pxj = J.cc + J.sa * umj + J.ca * vmj - J.top;
                        float lj = J.phi - 1.0f;
                        if (pyj >= 0.f && pyj <= lj && pxj >= 0.f && pxj <= lj) {
                            taken = true; break;
                        }
                    }
                }
                if (taken) continue;
            }

            // final writer: bilinear sample + jitter + noise
            int y = (int)G.y0i + u;
            int x = (int)G.x0i + v;

            float sy = (py + 0.5f) * G.r - 0.5f;
            float sx = (px + 0.5f) * G.r - 0.5f;
            float fy = floorf(sy), fx = floorf(sx);
            float wy = sy - fy, wx = sx - fx;
            int y0c = min(max((int)fy, 0), PHp - 1);
            int y1c = min(y0c + 1, PHp - 1);
            int x0c = min(max((int)fx, 0), PWp - 1);
            int x1c = min(x0c + 1, PWp - 1);
            int o00 = (y0c * PWp + x0c) * 3;
            int o01 = (y0c * PWp + x1c) * 3;
            int o10 = (y1c * PWp + x0c) * 3;
            int o11 = (y1c * PWp + x1c) * 3;

            uint32_t nb = ((uint32_t)y * (uint32_t)Wim + (uint32_t)x) * 3u;
            uint32_t bits[3];
            tf3(G.k2a, G.k2b, nb, bits);

            float omy = 1.0f - wy, omx = 1.0f - wx;
            float w00 = omy * omx, w01 = omy * wx, w10 = wy * omx, w11 = wy * wx;
            size_t base = (((size_t)b * Him + y) * Wim + x) * 3;
            float res[3];
            #pragma unroll
            for (int c = 0; c < 3; c++) {
                float wc = (c == 0) ? w0 : ((c == 1) ? w1 : w2);
                float bc = (c == 0) ? b0 : ((c == 1) ? b1 : b2);
#define ADJ(pp) fminf(fmaxf(fminf(fmaxf(fmaf(wc, (pp), bc), -1.f), 1.f) + s, -1.f), 1.f)
                float samp = ADJ(patch[o00 + c]) * w00 + ADJ(patch[o01 + c]) * w01
                           + ADJ(patch[o10 + c]) * w10 + ADJ(patch[o11 + c]) * w11;
#undef ADJ
                float noise = fmaxf(-0.1f, fmaf(bits_to_unit(bits[c]), 0.2f, -0.1f));
                res[c] = fminf(fmaxf(samp + noise + G.bright, -1.0f), 1.0f);
            }

            float i0 = images[base], i1 = images[base + 1], i2 = images[base + 2];
            oimg[base]      = res[0]; oimg[base + 1]  = res[1]; oimg[base + 2]  = res[2];
            omask[base]     = i0 - res[0];
            omask[base + 1] = i1 - res[1];
            omask[base + 2] = i2 - res[2];
        }
    }
}

// ---------------------------------------------------------------------------
extern "C" void kernel_launch(void* const* d_in, const int* in_sizes, int n_in,
                              void* d_out, int out_size) {
    const float* boxes  = (const float*)d_in[0];
    const float* images = (const float*)d_in[1];
    const float* patch  = (const float*)d_in[2];
    const float* scale  = (const float*)d_in[3];
    float* out   = (float*)d_out;
    float* omask = out + (size_t)Bimg * IMG;

    k_prep<<<dim3(NIMG_CHUNK + NPAT_CHUNK + 1, 16), 256>>>(
        images, patch, boxes, scale, out, omask);
    k_s<<<16, 128>>>();
    k_heavy<<<dim3(32, Bimg * Nbox), 128>>>(images, patch, out, omask);

    (void)in_sizes; (void)n_in; (void)out_size;
}

// round 12
// speedup vs baseline: 1.0224x; 1.0224x over previous
#include <cuda_runtime.h>
#include <stdint.h>
#include <math.h>

#define Bimg 16
#define Nbox 16
#define Him  640
#define Wim  640
#define PHp  300
#define PWp  300
#define PTOT (PHp*PWp*3)
#define IMG  ((size_t)Him * Wim * 3)

// ---------------------------------------------------------------------------
// JAX threefry2x32 (20 rounds), partitionable random-bits convention
// ---------------------------------------------------------------------------
__device__ __forceinline__ void tf2x32(uint32_t k0, uint32_t k1,
                                       uint32_t x0, uint32_t x1,
                                       uint32_t& o0, uint32_t& o1) {
    uint32_t ks2 = k0 ^ k1 ^ 0x1BD11BDAu;
    x0 += k0; x1 += k1;
#define TF_RND(r) { x0 += x1; x1 = __funnelshift_l(x1, x1, (r)); x1 ^= x0; }
    TF_RND(13) TF_RND(15) TF_RND(26) TF_RND(6)
    x0 += k1;  x1 += ks2 + 1u;
    TF_RND(17) TF_RND(29) TF_RND(16) TF_RND(24)
    x0 += ks2; x1 += k0 + 2u;
    TF_RND(13) TF_RND(15) TF_RND(26) TF_RND(6)
    x0 += k0;  x1 += k1 + 3u;
    TF_RND(17) TF_RND(29) TF_RND(16) TF_RND(24)
    x0 += k1;  x1 += ks2 + 4u;
    TF_RND(13) TF_RND(15) TF_RND(26) TF_RND(6)
    x0 += ks2; x1 += k0 + 5u;
#undef TF_RND
    o0 = x0; o1 = x1;
}

__device__ __forceinline__ uint32_t rbits(uint32_t k0, uint32_t k1, uint64_t idx) {
    uint32_t a, b;
    tf2x32(k0, k1, (uint32_t)(idx >> 32), (uint32_t)idx, a, b);
    return a ^ b;
}

// 3 interleaved threefry chains, counters (c0, c0+1, c0+2), hi word = 0.
__device__ __forceinline__ void tf3(uint32_t k0, uint32_t k1, uint32_t c0,
                                    uint32_t out[3]) {
    uint32_t ks2 = k0 ^ k1 ^ 0x1BD11BDAu;
    uint32_t a0 = k0, a1 = k0, a2 = k0;
    uint32_t b0 = c0 + k1, b1 = c0 + 1u + k1, b2 = c0 + 2u + k1;
#define R3(r)  { a0 += b0; b0 = __funnelshift_l(b0,b0,(r)); b0 ^= a0; \
                 a1 += b1; b1 = __funnelshift_l(b1,b1,(r)); b1 ^= a1; \
                 a2 += b2; b2 = __funnelshift_l(b2,b2,(r)); b2 ^= a2; }
#define INJ3(ka, kb) { a0 += (ka); b0 += (kb); a1 += (ka); b1 += (kb); a2 += (ka); b2 += (kb); }
    R3(13) R3(15) R3(26) R3(6)
    INJ3(k1, ks2 + 1u)
    R3(17) R3(29) R3(16) R3(24)
    INJ3(ks2, k0 + 2u)
    R3(13) R3(15) R3(26) R3(6)
    INJ3(k0, k1 + 3u)
    R3(17) R3(29) R3(16) R3(24)
    INJ3(k1, ks2 + 4u)
    R3(13) R3(15) R3(26) R3(6)
    out[0] = (a0 + ks2) ^ (b0 + k0 + 5u);
    out[1] = (a1 + ks2) ^ (b1 + k0 + 5u);
    out[2] = (a2 + ks2) ^ (b2 + k0 + 5u);
#undef R3
#undef INJ3
}

__device__ __forceinline__ float bits_to_unit(uint32_t bits) {
    return __uint_as_float((bits >> 9) | 0x3f800000u) - 1.0f;
}

__device__ __forceinline__ float juniform(uint32_t k0, uint32_t k1, uint64_t i,
                                          float lo, float hi) {
    float f = bits_to_unit(rbits(k0, k1, i));
    return fmaxf(lo, f * (hi - lo) + lo);
}

__device__ __forceinline__ float erfinv_xla(float x) {
    float w = -log1pf(-x * x);
    float p;
    if (w < 5.0f) {
        w -= 2.5f;
        p = 2.81022636e-08f;
        p = fmaf(p, w, 3.43273939e-07f);
        p = fmaf(p, w, -3.5233877e-06f);
        p = fmaf(p, w, -4.39150654e-06f);
        p = fmaf(p, w, 0.00021858087f);
        p = fmaf(p, w, -0.00125372503f);
        p = fmaf(p, w, -0.00417768164f);
        p = fmaf(p, w, 0.246640727f);
        p = fmaf(p, w, 1.50140941f);
    } else {
        w = sqrtf(w) - 3.0f;
        p = -0.000200214257f;
        p = fmaf(p, w, 0.000100950558f);
        p = fmaf(p, w, 0.00134934322f);
        p = fmaf(p, w, -0.00367342844f);
        p = fmaf(p, w, 0.00573950773f);
        p = fmaf(p, w, -0.0076224613f);
        p = fmaf(p, w, 0.00943887047f);
        p = fmaf(p, w, 1.00167406f);
        p = fmaf(p, w, 2.83297682f);
    }
    return p * x;
}

__device__ __forceinline__ float jnormal(uint32_t k0, uint32_t k1, uint64_t i) {
    const float lo = -0.99999994f;
    float u = juniform(k0, k1, i, lo, 1.0f);
    return 1.41421354f * erfinv_xla(u);
}

__device__ __forceinline__ void wb_for(int b, float w[3], float bb[3]) {
    uint32_t ib0, ib1;
    tf2x32(0u, 42u, 0u, (uint32_t)b, ib0, ib1);
    uint32_t kw0, kw1, kB0, kB1;
    tf2x32(ib0, ib1, 0u, 0u, kw0, kw1);
    tf2x32(ib0, ib1, 0u, 1u, kB0, kB1);
    #pragma unroll
    for (int c = 0; c < 3; c++) {
        w[c]  = jnormal(kw0, kw1, (uint64_t)c) * 0.1f + 0.5f;
        bb[c] = jnormal(kB0, kB1, (uint64_t)c) * 0.01f;
    }
}

// ---------------------------------------------------------------------------
// Device scratch
// ---------------------------------------------------------------------------
struct Geo {
    float y0i, x0i, diagi, phi, cc, top, r, ca, sa, bright;
    uint32_t k2a, k2b;
    int valid;
    int pad;
};                                      // 14 words

#define NIMG_CHUNK 128
#define NPAT_CHUNK 8

__device__ Geo      g_geo[Bimg][Nbox];
__device__ float    g_w[Bimg][3];
__device__ float    g_bj[Bimg][3];
__device__ float    g_isum[Bimg][NIMG_CHUNK];
__device__ float    g_psum[Bimg][NPAT_CHUNK];
__device__ float    g_s[Bimg];
__device__ unsigned g_later[Bimg][Nbox];

// ---------------------------------------------------------------------------
// K1 (k_prep): streaming copy+zero with fused image sums; patch sums;
// geometry + later-writer masks. grid (128+8+1, 16), 256 thr.  [R10 build]
// ---------------------------------------------------------------------------
__global__ void k_prep(const float* __restrict__ images,
                       const float* __restrict__ patch,
                       const float* __restrict__ boxes,
                       const float* __restrict__ scale_p,
                       float* __restrict__ oimg,
                       float* __restrict__ omask) {
    int b = blockIdx.y, g = blockIdx.x;

    if (g == NIMG_CHUNK + NPAT_CHUNK) {
        __shared__ Geo sgeo[Nbox];
        int n = threadIdx.x;
        if (n == 0) {
            float w[3], bb[3];
            wb_for(b, w, bb);
            #pragma unroll
            for (int c = 0; c < 3; c++) { g_w[b][c] = w[c]; g_bj[b][c] = bb[c]; }
        }
        if (n < Nbox) {
            float scale = scale_p[0];
            uint32_t ib0, ib1, kl0, kl1;
            tf2x32(0u, 42u, 0u, (uint32_t)b, ib0, ib1);
            tf2x32(ib0, ib1, 0u, 2u, kl0, kl1);
            uint32_t kn0, kn1;
            tf2x32(kl0, kl1, 0u, (uint32_t)n, kn0, kn1);
            uint32_t k10, k11, k20, k21, k30, k31;
            tf2x32(kn0, kn1, 0u, 0u, k10, k11);
            tf2x32(kn0, kn1, 0u, 1u, k20, k21);
            tf2x32(kn0, kn1, 0u, 2u, k30, k31);

            const float MAXA = (float)(20.0 * 3.14159265358979323846 / 180.0);
            float angle  = juniform(k10, k11, 0ull, -MAXA, MAXA);
            float bright = juniform(k30, k31, 0ull, -0.3f, 0.3f);

            const float* bx = boxes + ((size_t)b * Nbox + n) * 4;
            float ymin = bx[0], xmin = bx[1], ymax = bx[2], xmax = bx[3];
            float h  = ymax - ymin;
            float ww = xmax - xmin;
            float longer = fmaxf(h, ww);
            float ps   = floorf(longer * scale);
            float diag = fminf(sqrtf(2.0f) * ps, (float)Wim);
            float oy = ymin + h * 0.5f;
            float ox = xmin + ww * 0.5f;
            float y0 = fmaxf(oy - diag * 0.5f, 0.0f);
            float x0 = fmaxf(ox - diag * 0.5f, 0.0f);
            y0 = (y0 + diag > (float)Him) ? ((float)Him - diag) : y0;
            x0 = (x0 + diag > (float)Wim) ? ((float)Wim - diag) : x0;
            float phi   = fmaxf(floorf(ps), 1.0f);
            float diagi = floorf(diag);

            Geo gg;
            gg.y0i = floorf(y0); gg.x0i = floorf(x0);
            gg.diagi = diagi; gg.phi = phi;
            gg.cc  = (diagi - 1.0f) * 0.5f;
            gg.top = floorf((diagi - phi) * 0.5f);
            gg.r   = 300.0f / phi;
            gg.ca  = cosf(angle);
            gg.sa  = sinf(angle);
            gg.bright = bright;
            gg.k2a = k20; gg.k2b = k21;
            gg.valid = (phi * phi > 60.0f) ? 1 : 0;
            gg.pad = 0;
            g_geo[b][n] = gg;
            sgeo[n] = gg;
        }
        __syncthreads();
        if (n < Nbox) {
            const Geo& N = sgeo[n];
            unsigned m = 0;
            for (int j = n + 1; j < Nbox; j++) {
                const Geo& J = sgeo[j];
                if (J.valid &&
                    N.y0i < J.y0i + J.diagi && N.y0i + N.diagi > J.y0i &&
                    N.x0i < J.x0i + J.diagi && N.x0i + N.diagi > J.x0i)
                    m |= 1u << j;
            }
            g_later[b][n] = m;
        }
        return;
    }

    float acc = 0.0f;
    if (g < NIMG_CHUNK) {
        size_t base = (size_t)b * IMG + (size_t)g * (IMG / NIMG_CHUNK);
        const float4* src  = (const float4*)(images + base);
        float4* dimg = (float4*)(oimg + base);
        float4* dmsk = (float4*)(omask + base);
        const int nvec = (int)((IMG / NIMG_CHUNK) / 4);   // 2400 float4s
        const float4 z = make_float4(0.f, 0.f, 0.f, 0.f);
        float a0 = 0.f, a1 = 0.f, a2 = 0.f, a3 = 0.f;
        int i = threadIdx.x;
        if (i + 1792 < nvec) {
            float4 v0 = __ldcs(src + i);
            float4 v1 = __ldcs(src + i + 256);
            float4 v2 = __ldcs(src + i + 512);
            float4 v3 = __ldcs(src + i + 768);
            float4 v4 = __ldcs(src + i + 1024);
            float4 v5 = __ldcs(src + i + 1280);
            float4 v6 = __ldcs(src + i + 1536);
            float4 v7 = __ldcs(src + i + 1792);
            __stcs(dimg + i,        v0); __stcs(dimg + i + 256,  v1);
            __stcs(dimg + i + 512,  v2); __stcs(dimg + i + 768,  v3);
            __stcs(dimg + i + 1024, v4); __stcs(dimg + i + 1280, v5);
            __stcs(dimg + i + 1536, v6); __stcs(dimg + i + 1792, v7);
            __stcs(dmsk + i,        z);  __stcs(dmsk + i + 256,  z);
            __stcs(dmsk + i + 512,  z);  __stcs(dmsk + i + 768,  z);
            __stcs(dmsk + i + 1024, z);  __stcs(dmsk + i + 1280, z);
            __stcs(dmsk + i + 1536, z);  __stcs(dmsk + i + 1792, z);
            a0 += (v0.x + v0.y) + (v0.z + v0.w);
            a1 += (v1.x + v1.y) + (v1.z + v1.w);
            a2 += (v2.x + v2.y) + (v2.z + v2.w);
            a3 += (v3.x + v3.y) + (v3.z + v3.w);
            a0 += (v4.x + v4.y) + (v4.z + v4.w);
            a1 += (v5.x + v5.y) + (v5.z + v5.w);
            a2 += (v6.x + v6.y) + (v6.z + v6.w);
            a3 += (v7.x + v7.y) + (v7.z + v7.w);
            i += 2048;
        }
        for (; i < nvec; i += 256) {
            float4 v = __ldcs(src + i);
            __stcs(dimg + i, v);
            __stcs(dmsk + i, z);
            a0 += (v.x + v.y) + (v.z + v.w);
        }
        acc = (a0 + a1) + (a2 + a3);
    } else {
        float w[3], bb[3];
        wb_for(b, w, bb);
        int gp = g - NIMG_CHUNK;
        int chunk = PTOT / NPAT_CHUNK;                    // 33750
        int base = gp * chunk;
        float a0 = 0.f, a1 = 0.f;
        int i = base + threadIdx.x;
        int end = base + chunk;
        for (; i + 256 < end; i += 512) {
            int c0 = i % 3;
            int c1 = (i + 256) % 3;
            a0 += fminf(fmaxf(w[c0] * patch[i] + bb[c0], -1.0f), 1.0f);
            a1 += fminf(fmaxf(w[c1] * patch[i + 256] + bb[c1], -1.0f), 1.0f);
        }
        if (i < end) {
            int c = i % 3;
            a0 += fminf(fmaxf(w[c] * patch[i] + bb[c], -1.0f), 1.0f);
        }
        acc = a0 + a1;
    }
    __shared__ float sh[256];
    sh[threadIdx.x] = acc;
    __syncthreads();
    for (int s = 128; s > 0; s >>= 1) {
        if (threadIdx.x < s) sh[threadIdx.x] += sh[threadIdx.x + s];
        __syncthreads();
    }
    if (threadIdx.x == 0) {
        if (g < NIMG_CHUNK) g_isum[b][g] = sh[0];
        else                g_psum[b][g - NIMG_CHUNK] = sh[0];
    }
}

// ---------------------------------------------------------------------------
// K2 (k_s): finalize per-image brightness shift. grid (16), 32 thr.
// ---------------------------------------------------------------------------
__global__ void k_s() {
    int b = blockIdx.x;
    int l = threadIdx.x;
    float si = g_isum[b][l] + g_isum[b][l + 32]
             + g_isum[b][l + 64] + g_isum[b][l + 96];
    float sp = (l < NPAT_CHUNK) ? g_psum[b][l] : 0.0f;
    #pragma unroll
    for (int o = 16; o > 0; o >>= 1) {
        si += __shfl_down_sync(0xffffffffu, si, o);
        sp += __shfl_down_sync(0xffffffffu, sp, o);
    }
    if (l == 0) g_s[b] = si / 1228800.0f - sp / 270000.0f;
}

// ---------------------------------------------------------------------------
// K3 (k_heavy): warp-per-row; conservative v-interval; per-pixel software
// pipeline: issue all 15 loads first, run tf3 under them, then combine.
// Exact accept tests preserved verbatim. grid (32, 256), block 128.
// ---------------------------------------------------------------------------
__global__ void k_heavy(const float* __restrict__ images,
                        const float* __restrict__ patch,
                        float* __restrict__ oimg,
                        float* __restrict__ omask) {
    int bz = blockIdx.y;
    int b = bz >> 4, n = bz & 15;

    const Geo G = g_geo[b][n];          // uniform broadcast loads
    if (!G.valid) return;
    int diag = (int)G.diagi;
    int warp = threadIdx.x >> 5;
    int lane = threadIdx.x & 31;

    float s  = g_s[b];
    float w0 = g_w[b][0],  w1 = g_w[b][1],  w2 = g_w[b][2];
    float b0 = g_bj[b][0], b1 = g_bj[b][1], b2 = g_bj[b][2];
    unsigned later = g_later[b][n];
    float lim = G.phi - 1.0f;

    for (int u = blockIdx.x * 4 + warp; u < diag; u += 128) {
        float uf = (float)u;
        // py(v) = P0 - sa*v ; px(v) = Q0 + ca*v   (rearranged ONLY for bounds)
        float P0 = G.cc + G.ca * (uf - G.cc) + G.sa * G.cc - G.top;
        float Q0 = G.cc + G.sa * (uf - G.cc) - G.ca * G.cc - G.top;
        float lo = (0.0f - Q0) / G.ca;
        float hi = (lim  - Q0) / G.ca;
        if (G.sa > 1e-8f) {
            lo = fmaxf(lo, (P0 - lim) / G.sa);
            hi = fminf(hi, P0 / G.sa);
        } else if (G.sa < -1e-8f) {
            lo = fmaxf(lo, P0 / G.sa);
            hi = fminf(hi, (P0 - lim) / G.sa);
        }
        int v0 = max(0, (int)floorf(lo) - 2);
        int v1 = min(diag - 1, (int)ceilf(hi) + 2);

        // row-level prune of later-box candidates (row test is exact & uniform)
        unsigned rmask = 0;
        {
            float yab = G.y0i + uf;
            unsigned mm = later;
            while (mm) {
                int j = __ffs(mm) - 1;
                mm &= mm - 1;
                const Geo J = g_geo[b][j];
                float uj = yab - J.y0i;
                if (uj >= 0.f && uj < J.diagi) rmask |= 1u << j;
            }
        }

        for (int v = v0 + lane; v <= v1; v += 32) {
            float vf = (float)v;
            // EXACT valid_src test (identical expression to prior rounds)
            float um = uf - G.cc, vm = vf - G.cc;
            float py = G.cc + G.ca * um - G.sa * vm - G.top;
            float px = G.cc + G.sa * um + G.ca * vm - G.top;
            if (!(py >= 0.0f && py <= lim && px >= 0.0f && px <= lim)) continue;

            // skip if any LATER box also writes this pixel (row bits pre-pruned)
            if (rmask) {
                float yab = G.y0i + uf, xab = G.x0i + vf;
                unsigned mm = rmask;
                bool taken = false;
                while (mm) {
                    int j = __ffs(mm) - 1;
                    mm &= mm - 1;
                    const Geo J = g_geo[b][j];
                    float uj = yab - J.y0i, vj = xab - J.x0i;
                    if (uj >= 0.f && vj >= 0.f && uj < J.diagi && vj < J.diagi) {
                        float umj = uj - J.cc, vmj = vj - J.cc;
                        float pyj = J.cc + J.ca * umj - J.sa * vmj - J.top;
                        float pxj = J.cc + J.sa * umj + J.ca * vmj - J.top;
                        float lj = J.phi - 1.0f;
                        if (pyj >= 0.f && pyj <= lj && pxj >= 0.f && pxj <= lj) {
                            taken = true; break;
                        }
                    }
                }
                if (taken) continue;
            }

            // ---- final writer: software-pipelined pixel ----
            int y = (int)G.y0i + u;
            int x = (int)G.x0i + v;

            // 1) addresses
            float sy = (py + 0.5f) * G.r - 0.5f;
            float sx = (px + 0.5f) * G.r - 0.5f;
            float fy = floorf(sy), fx = floorf(sx);
            float wy = sy - fy, wx = sx - fx;
            int y0c = min(max((int)fy, 0), PHp - 1);
            int y1c = min(y0c + 1, PHp - 1);
            int x0c = min(max((int)fx, 0), PWp - 1);
            int x1c = min(x0c + 1, PWp - 1);
            int o00 = (y0c * PWp + x0c) * 3;
            int o01 = (y0c * PWp + x1c) * 3;
            int o10 = (y1c * PWp + x0c) * 3;
            int o11 = (y1c * PWp + x1c) * 3;
            size_t base = (((size_t)b * Him + y) * Wim + x) * 3;

            // 2) issue ALL loads (12 patch taps + 3 image) before tf3
            float p00_0 = patch[o00 + 0], p00_1 = patch[o00 + 1], p00_2 = patch[o00 + 2];
            float p01_0 = patch[o01 + 0], p01_1 = patch[o01 + 1], p01_2 = patch[o01 + 2];
            float p10_0 = patch[o10 + 0], p10_1 = patch[o10 + 1], p10_2 = patch[o10 + 2];
            float p11_0 = patch[o11 + 0], p11_1 = patch[o11 + 1], p11_2 = patch[o11 + 2];
            float i0 = images[base], i1 = images[base + 1], i2 = images[base + 2];

            // 3) tf3 runs while loads are in flight
            uint32_t nb = ((uint32_t)y * (uint32_t)Wim + (uint32_t)x) * 3u;
            uint32_t bits[3];
            tf3(G.k2a, G.k2b, nb, bits);

            // 4) combine (arithmetic identical to prior rounds)
            float omy = 1.0f - wy, omx = 1.0f - wx;
            float w00 = omy * omx, w01 = omy * wx, w10 = wy * omx, w11 = wy * wx;
            float res[3];
#define ADJ2(pp, wc, bc) fminf(fmaxf(fminf(fmaxf(fmaf((wc), (pp), (bc)), -1.f), 1.f) + s, -1.f), 1.f)
            {
                float samp = ADJ2(p00_0, w0, b0) * w00 + ADJ2(p01_0, w0, b0) * w01
                           + ADJ2(p10_0, w0, b0) * w10 + ADJ2(p11_0, w0, b0) * w11;
                float noise = fmaxf(-0.1f, fmaf(bits_to_unit(bits[0]), 0.2f, -0.1f));
                res[0] = fminf(fmaxf(samp + noise + G.bright, -1.0f), 1.0f);
            }
            {
                float samp = ADJ2(p00_1, w1, b1) * w00 + ADJ2(p01_1, w1, b1) * w01
                           + ADJ2(p10_1, w1, b1) * w10 + ADJ2(p11_1, w1, b1) * w11;
                float noise = fmaxf(-0.1f, fmaf(bits_to_unit(bits[1]), 0.2f, -0.1f));
                res[1] = fminf(fmaxf(samp + noise + G.bright, -1.0f), 1.0f);
            }
            {
                float samp = ADJ2(p00_2, w2, b2) * w00 + ADJ2(p01_2, w2, b2) * w01
                           + ADJ2(p10_2, w2, b2) * w10 + ADJ2(p11_2, w2, b2) * w11;
                float noise = fmaxf(-0.1f, fmaf(bits_to_unit(bits[2]), 0.2f, -0.1f));
                res[2] = fminf(fmaxf(samp + noise + G.bright, -1.0f), 1.0f);
            }
#undef ADJ2

            oimg[base]      = res[0]; oimg[base + 1]  = res[1]; oimg[base + 2]  = res[2];
            omask[base]     = i0 - res[0];
            omask[base + 1] = i1 - res[1];
            omask[base + 2] = i2 - res[2];
        }
    }
}

// ---------------------------------------------------------------------------
extern "C" void kernel_launch(void* const* d_in, const int* in_sizes, int n_in,
                              void* d_out, int out_size) {
    const float* boxes  = (const float*)d_in[0];
    const float* images = (const float*)d_in[1];
    const float* patch  = (const float*)d_in[2];
    const float* scale  = (const float*)d_in[3];
    float* out   = (float*)d_out;
    float* omask = out + (size_t)Bimg * IMG;

    k_prep<<<dim3(NIMG_CHUNK + NPAT_CHUNK + 1, 16), 256>>>(
        images, patch, boxes, scale, out, omask);
    k_s<<<16, 32>>>();
    k_heavy<<<dim3(32, Bimg * Nbox), 128>>>(images, patch, out, omask);

    (void)in_sizes; (void)n_in; (void)out_size;
}

// round 13
// speedup vs baseline: 1.0535x; 1.0305x over previous
#include <cuda_runtime.h>
#include <stdint.h>
#include <math.h>

#define Bimg 16
#define Nbox 16
#define Him  640
#define Wim  640
#define PHp  300
#define PWp  300
#define PTOT (PHp*PWp*3)
#define IMG  ((size_t)Him * Wim * 3)

// ---------------------------------------------------------------------------
// JAX threefry2x32 (20 rounds), partitionable random-bits convention
// ---------------------------------------------------------------------------
__device__ __forceinline__ void tf2x32(uint32_t k0, uint32_t k1,
                                       uint32_t x0, uint32_t x1,
                                       uint32_t& o0, uint32_t& o1) {
    uint32_t ks2 = k0 ^ k1 ^ 0x1BD11BDAu;
    x0 += k0; x1 += k1;
#define TF_RND(r) { x0 += x1; x1 = __funnelshift_l(x1, x1, (r)); x1 ^= x0; }
    TF_RND(13) TF_RND(15) TF_RND(26) TF_RND(6)
    x0 += k1;  x1 += ks2 + 1u;
    TF_RND(17) TF_RND(29) TF_RND(16) TF_RND(24)
    x0 += ks2; x1 += k0 + 2u;
    TF_RND(13) TF_RND(15) TF_RND(26) TF_RND(6)
    x0 += k0;  x1 += k1 + 3u;
    TF_RND(17) TF_RND(29) TF_RND(16) TF_RND(24)
    x0 += k1;  x1 += ks2 + 4u;
    TF_RND(13) TF_RND(15) TF_RND(26) TF_RND(6)
    x0 += ks2; x1 += k0 + 5u;
#undef TF_RND
    o0 = x0; o1 = x1;
}

__device__ __forceinline__ uint32_t rbits(uint32_t k0, uint32_t k1, uint64_t idx) {
    uint32_t a, b;
    tf2x32(k0, k1, (uint32_t)(idx >> 32), (uint32_t)idx, a, b);
    return a ^ b;
}

// 3 interleaved threefry chains, counters (c0, c0+1, c0+2), hi word = 0.
__device__ __forceinline__ void tf3(uint32_t k0, uint32_t k1, uint32_t c0,
                                    uint32_t out[3]) {
    uint32_t ks2 = k0 ^ k1 ^ 0x1BD11BDAu;
    uint32_t a0 = k0, a1 = k0, a2 = k0;
    uint32_t b0 = c0 + k1, b1 = c0 + 1u + k1, b2 = c0 + 2u + k1;
#define R3(r)  { a0 += b0; b0 = __funnelshift_l(b0,b0,(r)); b0 ^= a0; \
                 a1 += b1; b1 = __funnelshift_l(b1,b1,(r)); b1 ^= a1; \
                 a2 += b2; b2 = __funnelshift_l(b2,b2,(r)); b2 ^= a2; }
#define INJ3(ka, kb) { a0 += (ka); b0 += (kb); a1 += (ka); b1 += (kb); a2 += (ka); b2 += (kb); }
    R3(13) R3(15) R3(26) R3(6)
    INJ3(k1, ks2 + 1u)
    R3(17) R3(29) R3(16) R3(24)
    INJ3(ks2, k0 + 2u)
    R3(13) R3(15) R3(26) R3(6)
    INJ3(k0, k1 + 3u)
    R3(17) R3(29) R3(16) R3(24)
    INJ3(k1, ks2 + 4u)
    R3(13) R3(15) R3(26) R3(6)
    out[0] = (a0 + ks2) ^ (b0 + k0 + 5u);
    out[1] = (a1 + ks2) ^ (b1 + k0 + 5u);
    out[2] = (a2 + ks2) ^ (b2 + k0 + 5u);
#undef R3
#undef INJ3
}

__device__ __forceinline__ float bits_to_unit(uint32_t bits) {
    return __uint_as_float((bits >> 9) | 0x3f800000u) - 1.0f;
}

__device__ __forceinline__ float juniform(uint32_t k0, uint32_t k1, uint64_t i,
                                          float lo, float hi) {
    float f = bits_to_unit(rbits(k0, k1, i));
    return fmaxf(lo, f * (hi - lo) + lo);
}

__device__ __forceinline__ float erfinv_xla(float x) {
    float w = -log1pf(-x * x);
    float p;
    if (w < 5.0f) {
        w -= 2.5f;
        p = 2.81022636e-08f;
        p = fmaf(p, w, 3.43273939e-07f);
        p = fmaf(p, w, -3.5233877e-06f);
        p = fmaf(p, w, -4.39150654e-06f);
        p = fmaf(p, w, 0.00021858087f);
        p = fmaf(p, w, -0.00125372503f);
        p = fmaf(p, w, -0.00417768164f);
        p = fmaf(p, w, 0.246640727f);
        p = fmaf(p, w, 1.50140941f);
    } else {
        w = sqrtf(w) - 3.0f;
        p = -0.000200214257f;
        p = fmaf(p, w, 0.000100950558f);
        p = fmaf(p, w, 0.00134934322f);
        p = fmaf(p, w, -0.00367342844f);
        p = fmaf(p, w, 0.00573950773f);
        p = fmaf(p, w, -0.0076224613f);
        p = fmaf(p, w, 0.00943887047f);
        p = fmaf(p, w, 1.00167406f);
        p = fmaf(p, w, 2.83297682f);
    }
    return p * x;
}

__device__ __forceinline__ float jnormal(uint32_t k0, uint32_t k1, uint64_t i) {
    const float lo = -0.99999994f;
    float u = juniform(k0, k1, i, lo, 1.0f);
    return 1.41421354f * erfinv_xla(u);
}

__device__ __forceinline__ void wb_for(int b, float w[3], float bb[3]) {
    uint32_t ib0, ib1;
    tf2x32(0u, 42u, 0u, (uint32_t)b, ib0, ib1);
    uint32_t kw0, kw1, kB0, kB1;
    tf2x32(ib0, ib1, 0u, 0u, kw0, kw1);
    tf2x32(ib0, ib1, 0u, 1u, kB0, kB1);
    #pragma unroll
    for (int c = 0; c < 3; c++) {
        w[c]  = jnormal(kw0, kw1, (uint64_t)c) * 0.1f + 0.5f;
        bb[c] = jnormal(kB0, kB1, (uint64_t)c) * 0.01f;
    }
}

// ---------------------------------------------------------------------------
// Device scratch
// ---------------------------------------------------------------------------
struct Geo {
    float y0i, x0i, diagi, phi, cc, top, r, ca, sa, bright;
    uint32_t k2a, k2b;
    int valid;
    int pad;
};                                      // 14 words

#define NIMG_CHUNK 128
#define NPAT_CHUNK 8

__device__ Geo      g_geo[Bimg][Nbox];
__device__ float    g_w[Bimg][3];
__device__ float    g_bj[Bimg][3];
__device__ float    g_isum[Bimg][NIMG_CHUNK];
__device__ float    g_psum[Bimg][NPAT_CHUNK];
__device__ float    g_s[Bimg];
__device__ unsigned g_later[Bimg][Nbox];

// ---------------------------------------------------------------------------
// K0 (k_misc): geometry + later masks + patch sums — all register-heavy code
// isolated from the copy kernel. grid (NPAT_CHUNK+1, 16), 256 thr.
// ---------------------------------------------------------------------------
__global__ void k_misc(const float* __restrict__ patch,
                       const float* __restrict__ boxes,
                       const float* __restrict__ scale_p) {
    int b = blockIdx.y, g = blockIdx.x;

    if (g == NPAT_CHUNK) {
        __shared__ Geo sgeo[Nbox];
        int n = threadIdx.x;
        if (n == 0) {
            float w[3], bb[3];
            wb_for(b, w, bb);
            #pragma unroll
            for (int c = 0; c < 3; c++) { g_w[b][c] = w[c]; g_bj[b][c] = bb[c]; }
        }
        if (n < Nbox) {
            float scale = scale_p[0];
            uint32_t ib0, ib1, kl0, kl1;
            tf2x32(0u, 42u, 0u, (uint32_t)b, ib0, ib1);
            tf2x32(ib0, ib1, 0u, 2u, kl0, kl1);
            uint32_t kn0, kn1;
            tf2x32(kl0, kl1, 0u, (uint32_t)n, kn0, kn1);
            uint32_t k10, k11, k20, k21, k30, k31;
            tf2x32(kn0, kn1, 0u, 0u, k10, k11);
            tf2x32(kn0, kn1, 0u, 1u, k20, k21);
            tf2x32(kn0, kn1, 0u, 2u, k30, k31);

            const float MAXA = (float)(20.0 * 3.14159265358979323846 / 180.0);
            float angle  = juniform(k10, k11, 0ull, -MAXA, MAXA);
            float bright = juniform(k30, k31, 0ull, -0.3f, 0.3f);

            const float* bx = boxes + ((size_t)b * Nbox + n) * 4;
            float ymin = bx[0], xmin = bx[1], ymax = bx[2], xmax = bx[3];
            float h  = ymax - ymin;
            float ww = xmax - xmin;
            float longer = fmaxf(h, ww);
            float ps   = floorf(longer * scale);
            float diag = fminf(sqrtf(2.0f) * ps, (float)Wim);
            float oy = ymin + h * 0.5f;
            float ox = xmin + ww * 0.5f;
            float y0 = fmaxf(oy - diag * 0.5f, 0.0f);
            float x0 = fmaxf(ox - diag * 0.5f, 0.0f);
            y0 = (y0 + diag > (float)Him) ? ((float)Him - diag) : y0;
            x0 = (x0 + diag > (float)Wim) ? ((float)Wim - diag) : x0;
            float phi   = fmaxf(floorf(ps), 1.0f);
            float diagi = floorf(diag);

            Geo gg;
            gg.y0i = floorf(y0); gg.x0i = floorf(x0);
            gg.diagi = diagi; gg.phi = phi;
            gg.cc  = (diagi - 1.0f) * 0.5f;
            gg.top = floorf((diagi - phi) * 0.5f);
            gg.r   = 300.0f / phi;
            gg.ca  = cosf(angle);
            gg.sa  = sinf(angle);
            gg.bright = bright;
            gg.k2a = k20; gg.k2b = k21;
            gg.valid = (phi * phi > 60.0f) ? 1 : 0;
            gg.pad = 0;
            g_geo[b][n] = gg;
            sgeo[n] = gg;
        }
        __syncthreads();
        if (n < Nbox) {
            const Geo& N = sgeo[n];
            unsigned m = 0;
            for (int j = n + 1; j < Nbox; j++) {
                const Geo& J = sgeo[j];
                if (J.valid &&
                    N.y0i < J.y0i + J.diagi && N.y0i + N.diagi > J.y0i &&
                    N.x0i < J.x0i + J.diagi && N.x0i + N.diagi > J.x0i)
                    m |= 1u << j;
            }
            g_later[b][n] = m;
        }
        return;
    }

    // patch partial sums
    float w[3], bb[3];
    wb_for(b, w, bb);
    int chunk = PTOT / NPAT_CHUNK;                    // 33750
    int base = g * chunk;
    float a0 = 0.f, a1 = 0.f;
    int i = base + threadIdx.x;
    int end = base + chunk;
    for (; i + 256 < end; i += 512) {
        int c0 = i % 3;
        int c1 = (i + 256) % 3;
        a0 += fminf(fmaxf(w[c0] * patch[i] + bb[c0], -1.0f), 1.0f);
        a1 += fminf(fmaxf(w[c1] * patch[i + 256] + bb[c1], -1.0f), 1.0f);
    }
    if (i < end) {
        int c = i % 3;
        a0 += fminf(fmaxf(w[c] * patch[i] + bb[c], -1.0f), 1.0f);
    }
    float acc = a0 + a1;

    __shared__ float sh[256];
    sh[threadIdx.x] = acc;
    __syncthreads();
    for (int s = 128; s > 0; s >>= 1) {
        if (threadIdx.x < s) sh[threadIdx.x] += sh[threadIdx.x + s];
        __syncthreads();
    }
    if (threadIdx.x == 0) g_psum[b][g] = sh[0];
}

// ---------------------------------------------------------------------------
// K1 (k_copy): ONLY streaming copy+zero+image-sum. Minimal registers.
// grid (128, 16), 256 thr; 2400 float4 per block.
// ---------------------------------------------------------------------------
__global__ void __launch_bounds__(256, 6)
k_copy(const float* __restrict__ images,
       float* __restrict__ oimg,
       float* __restrict__ omask) {
    int b = blockIdx.y, g = blockIdx.x;
    size_t base = (size_t)b * IMG + (size_t)g * (IMG / NIMG_CHUNK);
    const float4* src  = (const float4*)(images + base);
    float4* dimg = (float4*)(oimg + base);
    float4* dmsk = (float4*)(omask + base);
    const int nvec = (int)((IMG / NIMG_CHUNK) / 4);   // 2400 float4s
    const float4 z = make_float4(0.f, 0.f, 0.f, 0.f);
    float a0 = 0.f, a1 = 0.f, a2 = 0.f, a3 = 0.f;
    int i = threadIdx.x;
    for (; i + 768 < nvec; i += 1024) {
        float4 v0 = __ldcs(src + i);
        float4 v1 = __ldcs(src + i + 256);
        float4 v2 = __ldcs(src + i + 512);
        float4 v3 = __ldcs(src + i + 768);
        __stcs(dimg + i,       v0); __stcs(dimg + i + 256, v1);
        __stcs(dimg + i + 512, v2); __stcs(dimg + i + 768, v3);
        __stcs(dmsk + i,       z);  __stcs(dmsk + i + 256, z);
        __stcs(dmsk + i + 512, z);  __stcs(dmsk + i + 768, z);
        a0 += (v0.x + v0.y) + (v0.z + v0.w);
        a1 += (v1.x + v1.y) + (v1.z + v1.w);
        a2 += (v2.x + v2.y) + (v2.z + v2.w);
        a3 += (v3.x + v3.y) + (v3.z + v3.w);
    }
    for (; i < nvec; i += 256) {
        float4 v = __ldcs(src + i);
        __stcs(dimg + i, v);
        __stcs(dmsk + i, z);
        a0 += (v.x + v.y) + (v.z + v.w);
    }
    float acc = (a0 + a1) + (a2 + a3);

    __shared__ float sh[256];
    sh[threadIdx.x] = acc;
    __syncthreads();
    for (int s = 128; s > 32; s >>= 1) {
        if (threadIdx.x < s) sh[threadIdx.x] += sh[threadIdx.x + s];
        __syncthreads();
    }
    if (threadIdx.x < 32) {
        float v = sh[threadIdx.x] + sh[threadIdx.x + 32];
        #pragma unroll
        for (int o = 16; o > 0; o >>= 1)
            v += __shfl_down_sync(0xffffffffu, v, o);
        if (threadIdx.x == 0) g_isum[b][g] = v;
    }
}

// ---------------------------------------------------------------------------
// K2 (k_s): finalize per-image brightness shift. grid (16), 32 thr.
// ---------------------------------------------------------------------------
__global__ void k_s() {
    int b = blockIdx.x;
    int l = threadIdx.x;
    float si = g_isum[b][l] + g_isum[b][l + 32]
             + g_isum[b][l + 64] + g_isum[b][l + 96];
    float sp = (l < NPAT_CHUNK) ? g_psum[b][l] : 0.0f;
    #pragma unroll
    for (int o = 16; o > 0; o >>= 1) {
        si += __shfl_down_sync(0xffffffffu, si, o);
        sp += __shfl_down_sync(0xffffffffu, sp, o);
    }
    if (l == 0) g_s[b] = si / 1228800.0f - sp / 270000.0f;
}

// ---------------------------------------------------------------------------
// K3 (k_heavy): warp-per-row; conservative v-interval; per-pixel software
// pipeline. Exact accept tests preserved verbatim. grid (32, 256), block 128.
// ---------------------------------------------------------------------------
__global__ void k_heavy(const float* __restrict__ images,
                        const float* __restrict__ patch,
                        float* __restrict__ oimg,
                        float* __restrict__ omask) {
    int bz = blockIdx.y;
    int b = bz >> 4, n = bz & 15;

    const Geo G = g_geo[b][n];          // uniform broadcast loads
    if (!G.valid) return;
    int diag = (int)G.diagi;
    int warp = threadIdx.x >> 5;
    int lane = threadIdx.x & 31;

    float s  = g_s[b];
    float w0 = g_w[b][0],  w1 = g_w[b][1],  w2 = g_w[b][2];
    float b0 = g_bj[b][0], b1 = g_bj[b][1], b2 = g_bj[b][2];
    unsigned later = g_later[b][n];
    float lim = G.phi - 1.0f;

    for (int u = blockIdx.x * 4 + warp; u < diag; u += 128) {
        float uf = (float)u;
        float P0 = G.cc + G.ca * (uf - G.cc) + G.sa * G.cc - G.top;
        float Q0 = G.cc + G.sa * (uf - G.cc) - G.ca * G.cc - G.top;
        float lo = (0.0f - Q0) / G.ca;
        float hi = (lim  - Q0) / G.ca;
        if (G.sa > 1e-8f) {
            lo = fmaxf(lo, (P0 - lim) / G.sa);
            hi = fminf(hi, P0 / G.sa);
        } else if (G.sa < -1e-8f) {
            lo = fmaxf(lo, P0 / G.sa);
            hi = fminf(hi, (P0 - lim) / G.sa);
        }
        int v0 = max(0, (int)floorf(lo) - 2);
        int v1 = min(diag - 1, (int)ceilf(hi) + 2);

        unsigned rmask = 0;
        {
            float yab = G.y0i + uf;
            unsigned mm = later;
            while (mm) {
                int j = __ffs(mm) - 1;
                mm &= mm - 1;
                const Geo J = g_geo[b][j];
                float uj = yab - J.y0i;
                if (uj >= 0.f && uj < J.diagi) rmask |= 1u << j;
            }
        }

        for (int v = v0 + lane; v <= v1; v += 32) {
            float vf = (float)v;
            float um = uf - G.cc, vm = vf - G.cc;
            float py = G.cc + G.ca * um - G.sa * vm - G.top;
            float px = G.cc + G.sa * um + G.ca * vm - G.top;
            if (!(py >= 0.0f && py <= lim && px >= 0.0f && px <= lim)) continue;

            if (rmask) {
                float yab = G.y0i + uf, xab = G.x0i + vf;
                unsigned mm = rmask;
                bool taken = false;
                while (mm) {
                    int j = __ffs(mm) - 1;
                    mm &= mm - 1;
                    const Geo J = g_geo[b][j];
                    float uj = yab - J.y0i, vj = xab - J.x0i;
                    if (uj >= 0.f && vj >= 0.f && uj < J.diagi && vj < J.diagi) {
                        float umj = uj - J.cc, vmj = vj - J.cc;
                        float pyj = J.cc + J.ca * umj - J.sa * vmj - J.top;
                        float pxj = J.cc + J.sa * umj + J.ca * vmj - J.top;
                        float lj = J.phi - 1.0f;
                        if (pyj >= 0.f && pyj <= lj && pxj >= 0.f && pxj <= lj) {
                            taken = true; break;
                        }
                    }
                }
                if (taken) continue;
            }

            int y = (int)G.y0i + u;
            int x = (int)G.x0i + v;

            float sy = (py + 0.5f) * G.r - 0.5f;
            float sx = (px + 0.5f) * G.r - 0.5f;
            float fy = floorf(sy), fx = floorf(sx);
            float wy = sy - fy, wx = sx - fx;
            int y0c = min(max((int)fy, 0), PHp - 1);
            int y1c = min(y0c + 1, PHp - 1);
            int x0c = min(max((int)fx, 0), PWp - 1);
            int x1c = min(x0c + 1, PWp - 1);
            int o00 = (y0c * PWp + x0c) * 3;
            int o01 = (y0c * PWp + x1c) * 3;
            int o10 = (y1c * PWp + x0c) * 3;
            int o11 = (y1c * PWp + x1c) * 3;
            size_t base = (((size_t)b * Him + y) * Wim + x) * 3;

            float p00_0 = patch[o00 + 0], p00_1 = patch[o00 + 1], p00_2 = patch[o00 + 2];
            float p01_0 = patch[o01 + 0], p01_1 = patch[o01 + 1], p01_2 = patch[o01 + 2];
            float p10_0 = patch[o10 + 0], p10_1 = patch[o10 + 1], p10_2 = patch[o10 + 2];
            float p11_0 = patch[o11 + 0], p11_1 = patch[o11 + 1], p11_2 = patch[o11 + 2];
            float i0 = images[base], i1 = images[base + 1], i2 = images[base + 2];

            uint32_t nb = ((uint32_t)y * (uint32_t)Wim + (uint32_t)x) * 3u;
            uint32_t bits[3];
            tf3(G.k2a, G.k2b, nb, bits);

            float omy = 1.0f - wy, omx = 1.0f - wx;
            float w00 = omy * omx, w01 = omy * wx, w10 = wy * omx, w11 = wy * wx;
            float res[3];
#define ADJ2(pp, wc, bc) fminf(fmaxf(fminf(fmaxf(fmaf((wc), (pp), (bc)), -1.f), 1.f) + s, -1.f), 1.f)
            {
                float samp = ADJ2(p00_0, w0, b0) * w00 + ADJ2(p01_0, w0, b0) * w01
                           + ADJ2(p10_0, w0, b0) * w10 + ADJ2(p11_0, w0, b0) * w11;
                float noise = fmaxf(-0.1f, fmaf(bits_to_unit(bits[0]), 0.2f, -0.1f));
                res[0] = fminf(fmaxf(samp + noise + G.bright, -1.0f), 1.0f);
            }
            {
                float samp = ADJ2(p00_1, w1, b1) * w00 + ADJ2(p01_1, w1, b1) * w01
                           + ADJ2(p10_1, w1, b1) * w10 + ADJ2(p11_1, w1, b1) * w11;
                float noise = fmaxf(-0.1f, fmaf(bits_to_unit(bits[1]), 0.2f, -0.1f));
                res[1] = fminf(fmaxf(samp + noise + G.bright, -1.0f), 1.0f);
            }
            {
                float samp = ADJ2(p00_2, w2, b2) * w00 + ADJ2(p01_2, w2, b2) * w01
                           + ADJ2(p10_2, w2, b2) * w10 + ADJ2(p11_2, w2, b2) * w11;
                float noise = fmaxf(-0.1f, fmaf(bits_to_unit(bits[2]), 0.2f, -0.1f));
                res[2] = fminf(fmaxf(samp + noise + G.bright, -1.0f), 1.0f);
            }
#undef ADJ2

            oimg[base]      = res[0]; oimg[base + 1]  = res[1]; oimg[base + 2]  = res[2];
            omask[base]     = i0 - res[0];
            omask[base + 1] = i1 - res[1];
            omask[base + 2] = i2 - res[2];
        }
    }
}

// ---------------------------------------------------------------------------
extern "C" void kernel_launch(void* const* d_in, const int* in_sizes, int n_in,
                              void* d_out, int out_size) {
    const float* boxes  = (const float*)d_in[0];
    const float* images = (const float*)d_in[1];
    const float* patch  = (const float*)d_in[2];
    const float* scale  = (const float*)d_in[3];
    float* out   = (float*)d_out;
    float* omask = out + (size_t)Bimg * IMG;

    k_misc<<<dim3(NPAT_CHUNK + 1, 16), 256>>>(patch, boxes, scale);
    k_copy<<<dim3(NIMG_CHUNK, 16), 256>>>(images, out, omask);
    k_s<<<16, 32>>>();
    k_heavy<<<dim3(32, Bimg * Nbox), 128>>>(images, patch, out, omask);

    (void)in_sizes; (void)n_in; (void)out_size;
}